// round 12
// baseline (speedup 1.0000x reference)
#include <cuda_runtime.h>
#include <cuda_fp16.h>
#include <cstdint>

// Flow_68015102099543, two-kernel scheme:
//  K1 repack: x [4,16,450,480] fp32 -> g_xh [4][458][484][16] fp16 pixel-major,
//     halo cells never written (stay .bss zero -> padding baked in).
//  K2 conv:   R10's proven mma kernel (pixel-permuted B columns, gapped
//     conflict-free smem, coalesced float4 epilogue) with staging replaced by
//     predicate-free cp.async 16B copies from the repacked tensor.

#define HH 450
#define WW 480
#define HW (HH * WW)

#define HP_H 458        // padded rows: covers hp = h0 + h_s up to 457
#define HP_W 484        // padded cols: wp = w0 + w_s up to 481

#define CTA_H 8         // 8 warps x 1 output row
#define CTA_W 48
#define HSX 10          // staged rows
#define NWS 50          // staged w positions
#define ROWU 148        // 16B units per staged smem row
#define ROWB (ROWU * 16)

// 28.4 MB device scratch, zero-initialized at module load; halo never written.
__device__ uint4 g_xh[(size_t)4 * HP_H * HP_W * 2];

__device__ __forceinline__ uint32_t smem_u32(const void* p) {
    return (uint32_t)__cvta_generic_to_shared(p);
}

__device__ __forceinline__ void ldsm_x4(uint32_t& r0, uint32_t& r1, uint32_t& r2, uint32_t& r3,
                                        uint32_t a) {
    asm volatile("ldmatrix.sync.aligned.m8n8.x4.shared.b16 {%0,%1,%2,%3}, [%4];"
                 : "=r"(r0), "=r"(r1), "=r"(r2), "=r"(r3) : "r"(a));
}

__device__ __forceinline__ void mma_fp16(float* d, const uint32_t* a,
                                         uint32_t b0, uint32_t b1) {
    asm volatile("mma.sync.aligned.m16n8k16.row.col.f32.f16.f16.f32 "
                 "{%0,%1,%2,%3}, {%4,%5,%6,%7}, {%8,%9}, {%0,%1,%2,%3};"
                 : "+f"(d[0]), "+f"(d[1]), "+f"(d[2]), "+f"(d[3])
                 : "r"(a[0]), "r"(a[1]), "r"(a[2]), "r"(a[3]), "r"(b0), "r"(b1));
}

__device__ __forceinline__ void cp16(uint32_t dst, const void* src) {
    asm volatile("cp.async.ca.shared.global [%0], [%1], 16;"
                 :: "r"(dst), "l"(src) : "memory");
}

// staged placement: 16B unit for (w_s, half) — proven conflict-free gapped layout
__device__ __forceinline__ uint32_t unit_of(int w_s, int half_) {
    int sg = w_s + 2 * (w_s >> 2);
    return (uint32_t)(2 * sg + (half_ ^ ((sg >> 2) & 1)));
}

// ---------------- K1: repack fp32 NCHW -> fp16 pixel-major padded ----------------
__global__ void __launch_bounds__(256) repack_kernel(const float* __restrict__ x) {
    int p = blockIdx.x * 256 + threadIdx.x;
    if (p >= 4 * HW) return;
    int b = p / HW;
    int rem = p - b * HW;
    int h = rem / WW;
    int w = rem - h * WW;

    const float* src = x + (size_t)(b * 16) * HW + h * WW + w;
    uint32_t pk[8];
#pragma unroll
    for (int cc = 0; cc < 8; cc++) {
        float v0 = __ldg(src + (size_t)(2 * cc)     * HW);
        float v1 = __ldg(src + (size_t)(2 * cc + 1) * HW);
        __half2 h2 = __floats2half2_rn(v0, v1);
        pk[cc] = *(uint32_t*)&h2;
    }
    uint4* dst = &g_xh[((size_t)(b * HP_H + h + 1) * HP_W + (w + 1)) * 2];
    dst[0] = make_uint4(pk[0], pk[1], pk[2], pk[3]);
    dst[1] = make_uint4(pk[4], pk[5], pk[6], pk[7]);
}

// ---------------- K2: conv via mma, cp.async staging ----------------
__global__ void __launch_bounds__(256, 5) flow_cp_kernel(
    const float* __restrict__ comb,   // [16,144]
    const float* __restrict__ bias,   // [16]
    float* __restrict__ out)          // [4,16,450,480]
{
    __shared__ uint4 xs4[HSX * ROWU];         // 23680 B
    __shared__ uint4 ws4[9 * 16 * 2];         // 4608 B

    const int tid = threadIdx.x;
    const int b  = blockIdx.z;
    const int h0 = blockIdx.y * CTA_H;
    const int w0 = blockIdx.x * CTA_W;

    // ---- stage weights (fp32 -> fp16), proven scheme ----
    for (int idx = tid; idx < 9 * 16 * 16; idx += 256) {
        int i = idx >> 8, o = (idx >> 4) & 15, c = idx & 15;
        float v = comb[o * 144 + i * 16 + c];
        int half_ = c >> 3;
        int phys = (i * 16 + o) * 2 + (half_ ^ ((o >> 2) & 1));
        ((__half*)ws4)[phys * 8 + (c & 7)] = __float2half(v);
    }

    // ---- stage x tile via cp.async: 1000 16B units, no predication ----
    {
        const uint32_t xb = smem_u32(xs4);
        const size_t gbase = ((size_t)b * HP_H + h0) * HP_W + w0;   // (h_s,w_s)=(0,0)
#pragma unroll
        for (int k = 0; k < 4; k++) {
            int u = k * 256 + tid;
            if (u < 1000) {
                int h_s = u / 100;
                int rem = u - h_s * 100;
                int w_s = rem >> 1;
                int half_ = rem & 1;
                const uint4* src = &g_xh[(gbase + h_s * HP_W + w_s) * 2 + half_];
                cp16(xb + (uint32_t)(h_s * ROWU + unit_of(w_s, half_)) * 16u, src);
            }
        }
        asm volatile("cp.async.commit_group;" ::: "memory");
        asm volatile("cp.async.wait_group 0;" ::: "memory");
    }
    __syncthreads();

    const int wid  = tid >> 5;
    const int lane = tid & 31;
    const int h = h0 + wid;
    if (h >= HH) return;          // whole-warp exit; no further barriers

    const int og = lane >> 2;
    const float b0v = __ldg(bias + og);
    const float b8v = __ldg(bias + 8 + og);
    float accA[3][4], accB[3][4];
#pragma unroll
    for (int p = 0; p < 3; p++) {
        accA[p][0] = b0v; accA[p][1] = b0v; accA[p][2] = b8v; accA[p][3] = b8v;
        accB[p][0] = b0v; accB[p][1] = b0v; accB[p][2] = b8v; accB[p][3] = b8v;
    }

    const uint32_t wbase = smem_u32(ws4);
    const uint32_t xbase = smem_u32(xs4);

    // A-frag lane addressing (proven scheme)
    const int o_l   = ((lane >> 3) & 1) * 8 + (lane & 7);
    const int ahalf = (lane >> 4) & 1;
    const uint32_t aoff = (uint32_t)((o_l * 2 + (ahalf ^ ((o_l >> 2) & 1))) * 16);

    // B-frag lane params: permuted pixel map f = {0,1,4,5,8,9,12,13}
    const int bp    = lane & 7;
    const int fbp   = (bp & 1) | ((bp >> 1) << 2);
    const int qset  = (lane >> 4) & 1;
    const int bhalf = (lane >> 3) & 1;

#pragma unroll
    for (int i = 0; i < 9; i++) {
        const int dy = i / 3, dx = i % 3;
        uint32_t a[4];
        ldsm_x4(a[0], a[1], a[2], a[3], wbase + (uint32_t)i * 512u + aoff);
        const uint32_t rowoff = (uint32_t)((wid + dy) * ROWB);
#pragma unroll
        for (int p = 0; p < 3; p++) {
            const int w_s = p * 16 + dx + fbp + 2 * qset;
            const uint32_t addr = xbase + rowoff + unit_of(w_s, bhalf) * 16u;
            uint32_t r0, r1, r2, r3;
            ldsm_x4(r0, r1, r2, r3, addr);
            mma_fp16(accA[p], a, r0, r1);
            mma_fp16(accB[p], a, r2, r3);
        }
    }

    // ---- coalesced epilogue: float4 = 4 contiguous pixels per lane ----
    const int j = lane & 3;
    float* op0 = out + ((((size_t)b * 16 + og) * HH + h) * WW + w0 + 4 * j);
    float* op8 = op0 + (size_t)8 * HW;
#pragma unroll
    for (int p = 0; p < 3; p++) {
        float4 v0; v0.x = accA[p][0]; v0.y = accA[p][1]; v0.z = accB[p][0]; v0.w = accB[p][1];
        float4 v8; v8.x = accA[p][2]; v8.y = accA[p][3]; v8.z = accB[p][2]; v8.w = accB[p][3];
        *(float4*)(op0 + p * 16) = v0;
        *(float4*)(op8 + p * 16) = v8;
    }
}

extern "C" void kernel_launch(void* const* d_in, const int* in_sizes, int n_in,
                              void* d_out, int out_size) {
    const float* x    = (const float*)d_in[0];
    const float* comb = (const float*)d_in[1];
    const float* bias = (const float*)d_in[2];
    float* out = (float*)d_out;

    repack_kernel<<<(4 * HW + 255) / 256, 256>>>(x);
    dim3 grid(WW / CTA_W, (HH + CTA_H - 1) / CTA_H, 4);   // (10, 57, 4)
    flow_cp_kernel<<<grid, 256>>>(comb, bias, out);
}